// round 10
// baseline (speedup 1.0000x reference)
#include <cuda_runtime.h>
#include <cuda_bf16.h>
#include <cstdint>

#define NMAX 100000
#define EMAX 640000
#define HDIM 256

typedef __nv_bfloat16 bf16;

// ---- scratch (no allocations allowed) ----
__device__ int   g_rowptr[NMAX + 1];
__device__ int   g_cursor[NMAX];
__device__ int   g_srcs[EMAX];
__device__ float g_h[(size_t)NMAX * HDIM];                       // layer1 fp32 output (for agg2)
__device__ bf16  g_xh[(size_t)NMAX * 128], g_xl[(size_t)NMAX * 128];
__device__ bf16  g_ah[(size_t)NMAX * HDIM], g_al[(size_t)NMAX * HDIM];   // agg hi/lo
__device__ bf16  g_hh[(size_t)NMAX * HDIM], g_hl[(size_t)NMAX * HDIM];   // layer1 out hi/lo
__device__ bf16  g_wh[196608], g_wl[196608];                     // W1l|W1r|W2l|W2r hi/lo

// =================== CSR build ===================
__global__ void zero_cursor_k(int n) {
    int i = blockIdx.x * blockDim.x + threadIdx.x;
    if (i < n) g_cursor[i] = 0;
}
__global__ void count_deg_k(const int* __restrict__ dst, int e) {
    int i = blockIdx.x * blockDim.x + threadIdx.x;
    if (i < e) atomicAdd(&g_cursor[dst[i]], 1);
}
__global__ void scan_k(int n) {
    __shared__ int sums[1024];
    int tid = threadIdx.x;
    int chunk = (n + 1023) / 1024;
    int start = min(tid * chunk, n);
    int end   = min(start + chunk, n);
    int s = 0;
    for (int i = start; i < end; i++) s += g_cursor[i];
    sums[tid] = s;
    __syncthreads();
    for (int d = 1; d < 1024; d <<= 1) {
        int v = sums[tid];
        int u = (tid >= d) ? sums[tid - d] : 0;
        __syncthreads();
        sums[tid] = v + u;
        __syncthreads();
    }
    int run = (tid == 0) ? 0 : sums[tid - 1];
    for (int i = start; i < end; i++) {
        int dg = g_cursor[i];
        g_rowptr[i] = run;
        g_cursor[i] = run;
        run += dg;
    }
    if (start < n && end == n) g_rowptr[n] = run;
}
__global__ void scatter_k(const int* __restrict__ src, const int* __restrict__ dst, int e) {
    int i = blockIdx.x * blockDim.x + threadIdx.x;
    if (i < e) {
        int p = atomicAdd(&g_cursor[dst[i]], 1);
        g_srcs[p] = src[i];
    }
}

// =================== fp32 -> bf16 hi/lo split ===================
__device__ __forceinline__ void split_bf16(float v, bf16& h, bf16& l) {
    h = __float2bfloat16_rn(v);
    l = __float2bfloat16_rn(v - __bfloat162float(h));
}

__global__ void conv_split_k(const float* __restrict__ s, bf16* __restrict__ h,
                             bf16* __restrict__ l, int cnt) {
    int i = blockIdx.x * blockDim.x + threadIdx.x;
    if (i < cnt) {
        bf16 hh, ll;
        split_bf16(s[i], hh, ll);
        h[i] = hh;
        l[i] = ll;
    }
}

// =================== mean aggregation, W warps/node, 4-edge unrolled ===================
// Each warp covers 128 columns (4 per lane). D = W * 128.
template <int D, int W>
__global__ void agg_mean_split_k(const float* __restrict__ X,
                                 bf16* __restrict__ oh, bf16* __restrict__ ol, int n) {
    int gw = (blockIdx.x * blockDim.x + threadIdx.x) >> 5;
    int w = gw / W;                      // node
    int part = gw % W;                   // column half
    int lane = threadIdx.x & 31;
    if (w >= n) return;
    int beg = g_rowptr[w], end = g_rowptr[w + 1];
    const int co = part * 128 + lane;    // this lane's base column

    float acc[4] = {0.f, 0.f, 0.f, 0.f};
    int e = beg;
    for (; e + 3 < end; e += 4) {
        const float* x0 = X + (size_t)g_srcs[e]     * D + co;
        const float* x1 = X + (size_t)g_srcs[e + 1] * D + co;
        const float* x2 = X + (size_t)g_srcs[e + 2] * D + co;
        const float* x3 = X + (size_t)g_srcs[e + 3] * D + co;
        float v0[4], v1[4], v2[4], v3[4];
#pragma unroll
        for (int j = 0; j < 4; j++) v0[j] = __ldg(x0 + 32 * j);
#pragma unroll
        for (int j = 0; j < 4; j++) v1[j] = __ldg(x1 + 32 * j);
#pragma unroll
        for (int j = 0; j < 4; j++) v2[j] = __ldg(x2 + 32 * j);
#pragma unroll
        for (int j = 0; j < 4; j++) v3[j] = __ldg(x3 + 32 * j);
#pragma unroll
        for (int j = 0; j < 4; j++) acc[j] += (v0[j] + v1[j]) + (v2[j] + v3[j]);
    }
    for (; e < end; e++) {
        const float* x0 = X + (size_t)g_srcs[e] * D + co;
#pragma unroll
        for (int j = 0; j < 4; j++) acc[j] += __ldg(x0 + 32 * j);
    }
    float inv = 1.0f / (float)max(end - beg, 1);
#pragma unroll
    for (int j = 0; j < 4; j++) {
        bf16 hh, ll;
        split_bf16(acc[j] * inv, hh, ll);
        oh[(size_t)w * D + co + 32 * j] = hh;
        ol[(size_t)w * D + co + 32 * j] = ll;
    }
}

// =================== HMMA (mma.sync bf16, 2-term split) GEMM ===================
// out[M,256] = relu( Am @ Wl^T + Ax @ Wr^T + bias )
// 256 thr, BM=128, BN=128 (grid.y=2), warp tile 64x32, Kc=32, cp.async double buffer.
#define SROW        80
#define TILE_BYTES  (128 * SROW)        // 10240
#define STAGE_BYTES (4 * TILE_BYTES)    // 40960 (Ahi,Alo,Bhi,Blo)
#define GEMM_SMEM   (2 * STAGE_BYTES)   // 81920 -> 2 CTAs/SM

__device__ __forceinline__ void mma_bf16(float* c, uint32_t a0, uint32_t a1, uint32_t a2,
                                         uint32_t a3, uint32_t b0, uint32_t b1) {
    asm volatile(
        "mma.sync.aligned.m16n8k16.row.col.f32.bf16.bf16.f32 "
        "{%0,%1,%2,%3},{%4,%5,%6,%7},{%8,%9},{%0,%1,%2,%3};"
        : "+f"(c[0]), "+f"(c[1]), "+f"(c[2]), "+f"(c[3])
        : "r"(a0), "r"(a1), "r"(a2), "r"(a3), "r"(b0), "r"(b1));
}

__device__ __forceinline__ void cp16(uint32_t dst, const void* src, bool valid) {
    int sz = valid ? 16 : 0;
    asm volatile("cp.async.ca.shared.global [%0], [%1], 16, %2;"
                 :: "r"(dst), "l"(src), "r"(sz));
}
#define CP_COMMIT() asm volatile("cp.async.commit_group;")
#define CP_WAIT(N)  asm volatile("cp.async.wait_group %0;" :: "n"(N))

template <int K>
__device__ __forceinline__ void gemm_fill_stage(
    uint32_t st, int c, int m0, int n0, int n, int tid,
    const bf16* __restrict__ Amh, const bf16* __restrict__ Aml,
    const bf16* __restrict__ Axh, const bf16* __restrict__ Axl,
    const bf16* __restrict__ Wlh, const bf16* __restrict__ Wll,
    const bf16* __restrict__ Wrh, const bf16* __restrict__ Wrl)
{
    constexpr int CH = K / 32;
    const int part = c / CH;
    const int k0 = (c % CH) * 32;
    const bf16* Ah = part ? Axh : Amh;
    const bf16* Al = part ? Axl : Aml;
    const bf16* Bh = part ? Wrh : Wlh;
    const bf16* Bl = part ? Wrl : Wll;
#pragma unroll
    for (int i = 0; i < 2; i++) {
        int cc = i * 256 + tid;           // 0..511
        int r = cc >> 2, q = cc & 3;      // row, 16B chunk (8 bf16)
        int gr = m0 + r;
        bool av = gr < n;
        size_t ao = (size_t)gr * K + k0 + q * 8;
        uint32_t so = st + r * SROW + q * 16;
        cp16(so,                  Ah + (av ? ao : 0), av);
        cp16(so + TILE_BYTES,     Al + (av ? ao : 0), av);
        size_t bo = (size_t)(n0 + r) * K + k0 + q * 8;
        cp16(so + 2 * TILE_BYTES, Bh + bo, true);
        cp16(so + 3 * TILE_BYTES, Bl + bo, true);
    }
}

template <int K>
__global__ void __launch_bounds__(256, 2) gemm_mma_k(
    const bf16* __restrict__ Amh, const bf16* __restrict__ Aml,
    const bf16* __restrict__ Axh, const bf16* __restrict__ Axl,
    const bf16* __restrict__ Wlh, const bf16* __restrict__ Wll,
    const bf16* __restrict__ Wrh, const bf16* __restrict__ Wrl,
    const float* __restrict__ bias, float* __restrict__ out,
    bf16* __restrict__ oh, bf16* __restrict__ ol, int n, int split)
{
    extern __shared__ char sm[];
    const uint32_t smu = (uint32_t)__cvta_generic_to_shared(sm);
    const int tid = threadIdx.x, wid = tid >> 5, lane = tid & 31;
    const int gid = lane >> 2, tig = lane & 3;
    const int wm = wid >> 2, wn = wid & 3;        // 2 x 4 warp grid
    const int m0 = blockIdx.x * 128, n0 = blockIdx.y * 128;
    constexpr int CH = K / 32, C = 2 * CH;

    float acc[4][4][4];
#pragma unroll
    for (int a = 0; a < 4; a++)
#pragma unroll
        for (int b = 0; b < 4; b++)
#pragma unroll
            for (int q = 0; q < 4; q++) acc[a][b][q] = 0.f;

    gemm_fill_stage<K>(smu, 0, m0, n0, n, tid, Amh, Aml, Axh, Axl, Wlh, Wll, Wrh, Wrl);
    CP_COMMIT();

    for (int c = 0; c < C; c++) {
        int buf = c & 1;
        if (c + 1 < C) {
            gemm_fill_stage<K>(smu + (buf ^ 1) * STAGE_BYTES, c + 1, m0, n0, n, tid,
                               Amh, Aml, Axh, Axl, Wlh, Wll, Wrh, Wrl);
            CP_COMMIT();
            CP_WAIT(1);
        } else {
            CP_WAIT(0);
        }
        __syncthreads();
        const char* st = sm + buf * STAGE_BYTES;
#pragma unroll
        for (int step = 0; step < 2; step++) {
            const int kb = (step * 16 + tig * 2) * 2;   // byte offset of this thread's k pair
            uint32_t ah[4][4], al4[4][4], bh[4][2], bl[4][2];
#pragma unroll
            for (int mt = 0; mt < 4; mt++) {
                const char* base = st + (wm * 64 + mt * 16 + gid) * SROW + kb;
                ah[mt][0] = *reinterpret_cast<const uint32_t*>(base);
                ah[mt][1] = *reinterpret_cast<const uint32_t*>(base + 8 * SROW);
                ah[mt][2] = *reinterpret_cast<const uint32_t*>(base + 16);
                ah[mt][3] = *reinterpret_cast<const uint32_t*>(base + 8 * SROW + 16);
                const char* basel = base + TILE_BYTES;
                al4[mt][0] = *reinterpret_cast<const uint32_t*>(basel);
                al4[mt][1] = *reinterpret_cast<const uint32_t*>(basel + 8 * SROW);
                al4[mt][2] = *reinterpret_cast<const uint32_t*>(basel + 16);
                al4[mt][3] = *reinterpret_cast<const uint32_t*>(basel + 8 * SROW + 16);
            }
#pragma unroll
            for (int nt = 0; nt < 4; nt++) {
                const char* base = st + 2 * TILE_BYTES + (wn * 32 + nt * 8 + gid) * SROW + kb;
                bh[nt][0] = *reinterpret_cast<const uint32_t*>(base);
                bh[nt][1] = *reinterpret_cast<const uint32_t*>(base + 16);
                const char* basel = base + TILE_BYTES;
                bl[nt][0] = *reinterpret_cast<const uint32_t*>(basel);
                bl[nt][1] = *reinterpret_cast<const uint32_t*>(basel + 16);
            }
#pragma unroll
            for (int mt = 0; mt < 4; mt++)
#pragma unroll
                for (int nt = 0; nt < 4; nt++) {
                    mma_bf16(acc[mt][nt], ah[mt][0], ah[mt][1], ah[mt][2], ah[mt][3],
                             bh[nt][0], bh[nt][1]);
                    mma_bf16(acc[mt][nt], ah[mt][0], ah[mt][1], ah[mt][2], ah[mt][3],
                             bl[nt][0], bl[nt][1]);
                    mma_bf16(acc[mt][nt], al4[mt][0], al4[mt][1], al4[mt][2], al4[mt][3],
                             bh[nt][0], bh[nt][1]);
                }
        }
        __syncthreads();
    }

    // epilogue: +bias, relu; optional hi/lo bf16 side-output
#pragma unroll
    for (int mt = 0; mt < 4; mt++) {
        int r0 = m0 + wm * 64 + mt * 16 + gid;
        int r1 = r0 + 8;
#pragma unroll
        for (int nt = 0; nt < 4; nt++) {
            int col = n0 + wn * 32 + nt * 8 + tig * 2;
            float b0v = __ldg(bias + col), b1v = __ldg(bias + col + 1);
            float v00 = fmaxf(acc[mt][nt][0] + b0v, 0.f);
            float v01 = fmaxf(acc[mt][nt][1] + b1v, 0.f);
            float v10 = fmaxf(acc[mt][nt][2] + b0v, 0.f);
            float v11 = fmaxf(acc[mt][nt][3] + b1v, 0.f);
            if (r0 < n) {
                *reinterpret_cast<float2*>(out + (size_t)r0 * HDIM + col) = make_float2(v00, v01);
                if (split) {
                    bf16 h0, l0, h1, l1;
                    split_bf16(v00, h0, l0);
                    split_bf16(v01, h1, l1);
                    *reinterpret_cast<__nv_bfloat162*>(oh + (size_t)r0 * HDIM + col) =
                        __halves2bfloat162(h0, h1);
                    *reinterpret_cast<__nv_bfloat162*>(ol + (size_t)r0 * HDIM + col) =
                        __halves2bfloat162(l0, l1);
                }
            }
            if (r1 < n) {
                *reinterpret_cast<float2*>(out + (size_t)r1 * HDIM + col) = make_float2(v10, v11);
                if (split) {
                    bf16 h0, l0, h1, l1;
                    split_bf16(v10, h0, l0);
                    split_bf16(v11, h1, l1);
                    *reinterpret_cast<__nv_bfloat162*>(oh + (size_t)r1 * HDIM + col) =
                        __halves2bfloat162(h0, h1);
                    *reinterpret_cast<__nv_bfloat162*>(ol + (size_t)r1 * HDIM + col) =
                        __halves2bfloat162(l0, l1);
                }
            }
        }
    }
}

// =================== launch ===================
extern "C" void kernel_launch(void* const* d_in, const int* in_sizes, int n_in,
                              void* d_out, int out_size)
{
    const float* x   = (const float*)d_in[0];
    const int*   ei  = (const int*)d_in[1];
    const float* W1l = (const float*)d_in[2];
    const float* b1  = (const float*)d_in[3];
    const float* W1r = (const float*)d_in[4];
    const float* W2l = (const float*)d_in[5];
    const float* b2  = (const float*)d_in[6];
    const float* W2r = (const float*)d_in[7];
    float* out = (float*)d_out;

    int N_ = in_sizes[0] / 128;
    int E_ = in_sizes[1] / 2;
    const int* src = ei;
    const int* dst = ei + E_;

    void* p;
    cudaGetSymbolAddress(&p, g_h);   float* h  = (float*)p;
    cudaGetSymbolAddress(&p, g_xh);  bf16* xh = (bf16*)p;
    cudaGetSymbolAddress(&p, g_xl);  bf16* xl = (bf16*)p;
    cudaGetSymbolAddress(&p, g_ah);  bf16* ah = (bf16*)p;
    cudaGetSymbolAddress(&p, g_al);  bf16* al = (bf16*)p;
    cudaGetSymbolAddress(&p, g_hh);  bf16* hh = (bf16*)p;
    cudaGetSymbolAddress(&p, g_hl);  bf16* hl = (bf16*)p;
    cudaGetSymbolAddress(&p, g_wh);  bf16* wh = (bf16*)p;
    cudaGetSymbolAddress(&p, g_wl);  bf16* wl = (bf16*)p;

    cudaFuncSetAttribute(gemm_mma_k<128>, cudaFuncAttributeMaxDynamicSharedMemorySize, GEMM_SMEM);
    cudaFuncSetAttribute(gemm_mma_k<256>, cudaFuncAttributeMaxDynamicSharedMemorySize, GEMM_SMEM);

    // CSR build
    zero_cursor_k<<<(N_ + 255) / 256, 256>>>(N_);
    count_deg_k<<<(E_ + 255) / 256, 256>>>(dst, E_);
    scan_k<<<1, 1024>>>(N_);
    scatter_k<<<(E_ + 255) / 256, 256>>>(src, dst, E_);

    // operand conversions (x + 4 weight matrices)
    conv_split_k<<<(N_ * 128 + 255) / 256, 256>>>(x, xh, xl, N_ * 128);
    conv_split_k<<<(32768 + 255) / 256, 256>>>(W1l, wh + 0, wl + 0, 32768);
    conv_split_k<<<(32768 + 255) / 256, 256>>>(W1r, wh + 32768, wl + 32768, 32768);
    conv_split_k<<<(65536 + 255) / 256, 256>>>(W2l, wh + 65536, wl + 65536, 65536);
    conv_split_k<<<(65536 + 255) / 256, 256>>>(W2r, wh + 131072, wl + 131072, 65536);

    int mtiles = (N_ + 127) / 128;

    // layer 1 (1 warp/node)
    agg_mean_split_k<128, 1><<<(N_ * 32 + 255) / 256, 256>>>(x, ah, al, N_);
    gemm_mma_k<128><<<dim3(mtiles, 2), 256, GEMM_SMEM>>>(
        ah, al, xh, xl, wh + 0, wl + 0, wh + 32768, wl + 32768,
        b1, h, hh, hl, N_, 1);

    // layer 2 (2 warps/node)
    agg_mean_split_k<256, 2><<<(N_ * 64 + 255) / 256, 256>>>(h, ah, al, N_);
    gemm_mma_k<256><<<dim3(mtiles, 2), 256, GEMM_SMEM>>>(
        ah, al, hh, hl, wh + 65536, wl + 65536, wh + 131072, wl + 131072,
        b2, out, (bf16*)nullptr, (bf16*)nullptr, N_, 0);
}

// round 11
// speedup vs baseline: 1.4980x; 1.4980x over previous
#include <cuda_runtime.h>
#include <cuda_fp16.h>
#include <cstdint>

#define NMAX 100000
#define EMAX 640000
#define HDIM 256

// ---- scratch (no allocations allowed) ----
__device__ int    g_rowptr[NMAX + 1];
__device__ int    g_cursor[NMAX];
__device__ int    g_srcs[EMAX];
__device__ float  g_h[(size_t)NMAX * HDIM];                 // layer1 fp32 output (for agg2)
__device__ __half g_xh[(size_t)NMAX * 128];                 // x fp16
__device__ __half g_ah[(size_t)NMAX * HDIM];                // agg fp16
__device__ __half g_hh[(size_t)NMAX * HDIM];                // layer1 out fp16
__device__ __half g_wh[196608];                             // W1l|W1r|W2l|W2r fp16

// =================== CSR build ===================
__global__ void zero_cursor_k(int n) {
    int i = blockIdx.x * blockDim.x + threadIdx.x;
    if (i < n) g_cursor[i] = 0;
}
__global__ void count_deg_k(const int* __restrict__ dst, int e) {
    int i = blockIdx.x * blockDim.x + threadIdx.x;
    if (i < e) atomicAdd(&g_cursor[dst[i]], 1);
}
__global__ void scan_k(int n) {
    __shared__ int sums[1024];
    int tid = threadIdx.x;
    int chunk = (n + 1023) / 1024;
    int start = min(tid * chunk, n);
    int end   = min(start + chunk, n);
    int s = 0;
    for (int i = start; i < end; i++) s += g_cursor[i];
    sums[tid] = s;
    __syncthreads();
    for (int d = 1; d < 1024; d <<= 1) {
        int v = sums[tid];
        int u = (tid >= d) ? sums[tid - d] : 0;
        __syncthreads();
        sums[tid] = v + u;
        __syncthreads();
    }
    int run = (tid == 0) ? 0 : sums[tid - 1];
    for (int i = start; i < end; i++) {
        int dg = g_cursor[i];
        g_rowptr[i] = run;
        g_cursor[i] = run;
        run += dg;
    }
    if (start < n && end == n) g_rowptr[n] = run;
}
__global__ void scatter_k(const int* __restrict__ src, const int* __restrict__ dst, int e) {
    int i = blockIdx.x * blockDim.x + threadIdx.x;
    if (i < e) {
        int p = atomicAdd(&g_cursor[dst[i]], 1);
        g_srcs[p] = src[i];
    }
}

// =================== fp32 -> fp16 convert ===================
__global__ void conv_h_k(const float* __restrict__ s, __half* __restrict__ h, int cnt) {
    int i = blockIdx.x * blockDim.x + threadIdx.x;
    if (i < cnt) h[i] = __float2half_rn(s[i]);
}

// =================== mean aggregation (warp / node), 2-edge unrolled ===================
template <int D>
__global__ void agg_mean_h_k(const float* __restrict__ X, __half* __restrict__ oh, int n) {
    int w = (blockIdx.x * blockDim.x + threadIdx.x) >> 5;
    int lane = threadIdx.x & 31;
    if (w >= n) return;
    int beg = g_rowptr[w], end = g_rowptr[w + 1];
    float acc[D / 32];
#pragma unroll
    for (int j = 0; j < D / 32; j++) acc[j] = 0.f;
    int e = beg;
    for (; e + 1 < end; e += 2) {
        const float* x0 = X + (size_t)g_srcs[e] * D;
        const float* x1 = X + (size_t)g_srcs[e + 1] * D;
        float v0[D / 32], v1[D / 32];
#pragma unroll
        for (int j = 0; j < D / 32; j++) v0[j] = __ldg(x0 + lane + 32 * j);
#pragma unroll
        for (int j = 0; j < D / 32; j++) v1[j] = __ldg(x1 + lane + 32 * j);
#pragma unroll
        for (int j = 0; j < D / 32; j++) acc[j] += v0[j] + v1[j];
    }
    if (e < end) {
        const float* x0 = X + (size_t)g_srcs[e] * D;
#pragma unroll
        for (int j = 0; j < D / 32; j++) acc[j] += __ldg(x0 + lane + 32 * j);
    }
    float inv = 1.0f / (float)max(end - beg, 1);
#pragma unroll
    for (int j = 0; j < D / 32; j++)
        oh[(size_t)w * D + lane + 32 * j] = __float2half_rn(acc[j] * inv);
}

// =================== HMMA (mma.sync fp16 single-pass) GEMM ===================
// out[M,256] = relu( Am @ Wl^T + Ax @ Wr^T + bias )
// 256 thr, BM=128, BN=128 (grid.y=2), warp tile 64x32, Kc=32, cp.async double buffer.
#define SROW        80
#define TILE_BYTES  (128 * SROW)        // 10240
#define STAGE_BYTES (2 * TILE_BYTES)    // 20480 (A, B)
#define GEMM_SMEM   (2 * STAGE_BYTES)   // 40960 -> 2 CTAs/SM easily

__device__ __forceinline__ void mma_f16(float* c, uint32_t a0, uint32_t a1, uint32_t a2,
                                        uint32_t a3, uint32_t b0, uint32_t b1) {
    asm volatile(
        "mma.sync.aligned.m16n8k16.row.col.f32.f16.f16.f32 "
        "{%0,%1,%2,%3},{%4,%5,%6,%7},{%8,%9},{%0,%1,%2,%3};"
        : "+f"(c[0]), "+f"(c[1]), "+f"(c[2]), "+f"(c[3])
        : "r"(a0), "r"(a1), "r"(a2), "r"(a3), "r"(b0), "r"(b1));
}

__device__ __forceinline__ void cp16(uint32_t dst, const void* src, bool valid) {
    int sz = valid ? 16 : 0;
    asm volatile("cp.async.ca.shared.global [%0], [%1], 16, %2;"
                 :: "r"(dst), "l"(src), "r"(sz));
}
#define CP_COMMIT() asm volatile("cp.async.commit_group;")
#define CP_WAIT(N)  asm volatile("cp.async.wait_group %0;" :: "n"(N))

template <int K>
__device__ __forceinline__ void gemm_fill_stage(
    uint32_t st, int c, int m0, int n0, int n, int tid,
    const __half* __restrict__ Am, const __half* __restrict__ Ax,
    const __half* __restrict__ Wl, const __half* __restrict__ Wr)
{
    constexpr int CH = K / 32;
    const int part = c / CH;
    const int k0 = (c % CH) * 32;
    const __half* A = part ? Ax : Am;
    const __half* B = part ? Wr : Wl;
#pragma unroll
    for (int i = 0; i < 2; i++) {
        int cc = i * 256 + tid;           // 0..511
        int r = cc >> 2, q = cc & 3;      // row, 16B chunk (8 fp16)
        int gr = m0 + r;
        bool av = gr < n;
        size_t ao = (size_t)gr * K + k0 + q * 8;
        uint32_t so = st + r * SROW + q * 16;
        cp16(so,              A + (av ? ao : 0), av);
        size_t bo = (size_t)(n0 + r) * K + k0 + q * 8;
        cp16(so + TILE_BYTES, B + bo, true);
    }
}

template <int K>
__global__ void __launch_bounds__(256, 2) gemm_mma_k(
    const __half* __restrict__ Am, const __half* __restrict__ Ax,
    const __half* __restrict__ Wl, const __half* __restrict__ Wr,
    const float* __restrict__ bias, float* __restrict__ out,
    __half* __restrict__ oh, int n, int split)
{
    extern __shared__ char sm[];
    const uint32_t smu = (uint32_t)__cvta_generic_to_shared(sm);
    const int tid = threadIdx.x, wid = tid >> 5, lane = tid & 31;
    const int gid = lane >> 2, tig = lane & 3;
    const int wm = wid >> 2, wn = wid & 3;        // 2 x 4 warp grid
    const int m0 = blockIdx.x * 128, n0 = blockIdx.y * 128;
    constexpr int CH = K / 32, C = 2 * CH;

    float acc[4][4][4];
#pragma unroll
    for (int a = 0; a < 4; a++)
#pragma unroll
        for (int b = 0; b < 4; b++)
#pragma unroll
            for (int q = 0; q < 4; q++) acc[a][b][q] = 0.f;

    gemm_fill_stage<K>(smu, 0, m0, n0, n, tid, Am, Ax, Wl, Wr);
    CP_COMMIT();

    for (int c = 0; c < C; c++) {
        int buf = c & 1;
        if (c + 1 < C) {
            gemm_fill_stage<K>(smu + (buf ^ 1) * STAGE_BYTES, c + 1, m0, n0, n, tid,
                               Am, Ax, Wl, Wr);
            CP_COMMIT();
            CP_WAIT(1);
        } else {
            CP_WAIT(0);
        }
        __syncthreads();
        const char* st = sm + buf * STAGE_BYTES;
#pragma unroll
        for (int step = 0; step < 2; step++) {
            const int kb = (step * 16 + tig * 2) * 2;   // byte offset of this thread's k pair
            uint32_t ah[4][4], bh[4][2];
#pragma unroll
            for (int mt = 0; mt < 4; mt++) {
                const char* base = st + (wm * 64 + mt * 16 + gid) * SROW + kb;
                ah[mt][0] = *reinterpret_cast<const uint32_t*>(base);
                ah[mt][1] = *reinterpret_cast<const uint32_t*>(base + 8 * SROW);
                ah[mt][2] = *reinterpret_cast<const uint32_t*>(base + 16);
                ah[mt][3] = *reinterpret_cast<const uint32_t*>(base + 8 * SROW + 16);
            }
#pragma unroll
            for (int nt = 0; nt < 4; nt++) {
                const char* base = st + TILE_BYTES + (wn * 32 + nt * 8 + gid) * SROW + kb;
                bh[nt][0] = *reinterpret_cast<const uint32_t*>(base);
                bh[nt][1] = *reinterpret_cast<const uint32_t*>(base + 16);
            }
#pragma unroll
            for (int mt = 0; mt < 4; mt++)
#pragma unroll
                for (int nt = 0; nt < 4; nt++)
                    mma_f16(acc[mt][nt], ah[mt][0], ah[mt][1], ah[mt][2], ah[mt][3],
                            bh[nt][0], bh[nt][1]);
        }
        __syncthreads();
    }

    // epilogue: +bias, relu; optional fp16 side-output
#pragma unroll
    for (int mt = 0; mt < 4; mt++) {
        int r0 = m0 + wm * 64 + mt * 16 + gid;
        int r1 = r0 + 8;
#pragma unroll
        for (int nt = 0; nt < 4; nt++) {
            int col = n0 + wn * 32 + nt * 8 + tig * 2;
            float b0v = __ldg(bias + col), b1v = __ldg(bias + col + 1);
            float v00 = fmaxf(acc[mt][nt][0] + b0v, 0.f);
            float v01 = fmaxf(acc[mt][nt][1] + b1v, 0.f);
            float v10 = fmaxf(acc[mt][nt][2] + b0v, 0.f);
            float v11 = fmaxf(acc[mt][nt][3] + b1v, 0.f);
            if (r0 < n) {
                *reinterpret_cast<float2*>(out + (size_t)r0 * HDIM + col) = make_float2(v00, v01);
                if (split)
                    *reinterpret_cast<__half2*>(oh + (size_t)r0 * HDIM + col) =
                        __floats2half2_rn(v00, v01);
            }
            if (r1 < n) {
                *reinterpret_cast<float2*>(out + (size_t)r1 * HDIM + col) = make_float2(v10, v11);
                if (split)
                    *reinterpret_cast<__half2*>(oh + (size_t)r1 * HDIM + col) =
                        __floats2half2_rn(v10, v11);
            }
        }
    }
}

// =================== launch ===================
extern "C" void kernel_launch(void* const* d_in, const int* in_sizes, int n_in,
                              void* d_out, int out_size)
{
    const float* x   = (const float*)d_in[0];
    const int*   ei  = (const int*)d_in[1];
    const float* W1l = (const float*)d_in[2];
    const float* b1  = (const float*)d_in[3];
    const float* W1r = (const float*)d_in[4];
    const float* W2l = (const float*)d_in[5];
    const float* b2  = (const float*)d_in[6];
    const float* W2r = (const float*)d_in[7];
    float* out = (float*)d_out;

    int N_ = in_sizes[0] / 128;
    int E_ = in_sizes[1] / 2;
    const int* src = ei;
    const int* dst = ei + E_;

    void* p;
    cudaGetSymbolAddress(&p, g_h);   float*  h  = (float*)p;
    cudaGetSymbolAddress(&p, g_xh);  __half* xh = (__half*)p;
    cudaGetSymbolAddress(&p, g_ah);  __half* ah = (__half*)p;
    cudaGetSymbolAddress(&p, g_hh);  __half* hh = (__half*)p;
    cudaGetSymbolAddress(&p, g_wh);  __half* wh = (__half*)p;

    cudaFuncSetAttribute(gemm_mma_k<128>, cudaFuncAttributeMaxDynamicSharedMemorySize, GEMM_SMEM);
    cudaFuncSetAttribute(gemm_mma_k<256>, cudaFuncAttributeMaxDynamicSharedMemorySize, GEMM_SMEM);

    // CSR build
    zero_cursor_k<<<(N_ + 255) / 256, 256>>>(N_);
    count_deg_k<<<(E_ + 255) / 256, 256>>>(dst, E_);
    scan_k<<<1, 1024>>>(N_);
    scatter_k<<<(E_ + 255) / 256, 256>>>(src, dst, E_);

    // operand conversions (x + 4 weight matrices)
    conv_h_k<<<(N_ * 128 + 255) / 256, 256>>>(x, xh, N_ * 128);
    conv_h_k<<<(32768 + 255) / 256, 256>>>(W1l, wh + 0, 32768);
    conv_h_k<<<(32768 + 255) / 256, 256>>>(W1r, wh + 32768, 32768);
    conv_h_k<<<(65536 + 255) / 256, 256>>>(W2l, wh + 65536, 65536);
    conv_h_k<<<(65536 + 255) / 256, 256>>>(W2r, wh + 131072, 65536);

    int mtiles = (N_ + 127) / 128;

    // layer 1
    agg_mean_h_k<128><<<(N_ * 32 + 255) / 256, 256>>>(x, ah, N_);
    gemm_mma_k<128><<<dim3(mtiles, 2), 256, GEMM_SMEM>>>(
        ah, xh, wh + 0, wh + 32768, b1, h, hh, N_, 1);

    // layer 2
    agg_mean_h_k<256><<<(N_ * 32 + 255) / 256, 256>>>(h, ah, N_);
    gemm_mma_k<256><<<dim3(mtiles, 2), 256, GEMM_SMEM>>>(
        ah, hh, wh + 65536, wh + 131072, b2, out, (__half*)nullptr, N_, 0);
}